// round 10
// baseline (speedup 1.0000x reference)
#include <cuda_runtime.h>

#define VOCAB   50257
#define BEAM    8
#define BSZ     64
#define K       16
#define NGRAM   4
#define STEPDIM 16
#define SPLIT   8
#define CHUNK   6283    // ceil(50257/8)
#define T1      256
#define NLIST   (BEAM * SPLIT)   // 64 lists per row

typedef unsigned long long ull;

// Transposed scratch: [row][q][list] -> coalesced merge loads (lane == list).
__device__ ull      g_scratch[BSZ * K * NLIST];
__device__ unsigned g_count[BSZ];            // zero-init; reset after each use

// Monotone float -> uint32 encode: a > b  <=>  enc(a) > enc(b)
__device__ __forceinline__ unsigned int enc_f32(float v) {
    unsigned int u = __float_as_uint(v);
    return (u & 0x80000000u) ? ~u : (u | 0x80000000u);
}
// Key = [enc(value):32 | ~flat_index:32]: bigger key = bigger value, then
// smaller flat index (lax.top_k stable tie-break). Keys unique per row.
__device__ __forceinline__ ull make_key_enc(unsigned int ev, unsigned int flat) {
    return ((ull)ev << 32) | (unsigned int)(~flat);
}

// Sort a bitonic 16-sequence descending (static indexing -> registers).
__device__ __forceinline__ void bitonic16_desc(ull v[K]) {
    #pragma unroll
    for (int d = 8; d >= 1; d >>= 1) {
        #pragma unroll
        for (int i = 0; i < K; i++) {
            if ((i & d) == 0) {
                ull a = v[i], b = v[i | d];
                v[i]     = a > b ? a : b;
                v[i | d] = a > b ? b : a;
            }
        }
    }
}

// Merge own sorted-desc 16-list with xor-partner lane's list -> top-16 of
// union, sorted desc (both partners get the identical result).
__device__ __forceinline__ void warp_merge_round(ull v[K], int o) {
    ull other[K];
    #pragma unroll
    for (int i = 0; i < K; i++)
        other[i] = __shfl_xor_sync(0xffffffffu, v[K - 1 - i], o);
    #pragma unroll
    for (int i = 0; i < K; i++)
        v[i] = v[i] > other[i] ? v[i] : other[i];
    bitonic16_desc(v);
}

// Unrolled insert into sorted-desc 16-list (registers only).
__device__ __forceinline__ void insert16(ull best[K], ull key) {
    ull x = key;
    #pragma unroll
    for (int j = 0; j < K; j++) {
        ull mx = best[j] > x ? best[j] : x;
        ull mn = best[j] > x ? x : best[j];
        best[j] = mx;
        x = mn;
    }
}

// Pick v[lane] out of a register array without dynamic indexing.
__device__ __forceinline__ ull select_lane(const ull v[K], int lane) {
    ull r = v[0];
    #pragma unroll
    for (int j = 1; j < K; j++) if (lane == j) r = v[j];
    return r;
}

// Construct list l (beam = l>>3, chunk = l&7) of this row into dst[16]:
// kept beam -> load from scratch; non-kept -> analytic constant list
// (only chunk 0 carries it); step==0 -> only beam 0 exists.
__device__ __forceinline__ void build_list(ull dst[K], const ull* rowbase, int l,
                                           int step, unsigned keepmask, float bias) {
    const int beam = l >> 3, chunk = l & 7;
    const bool valid = !(step == 0 && beam != 0);
    const bool kb = (keepmask >> beam) & 1u;
    if (valid && kb) {
        #pragma unroll
        for (int q = 0; q < K; q++) dst[q] = rowbase[q * NLIST + l];
    } else if (valid && chunk == 0) {
        const unsigned int ev = enc_f32(bias);
        #pragma unroll
        for (int q = 0; q < K; q++)
            dst[q] = make_key_enc(ev, (unsigned)beam * VOCAB + (unsigned)q);
    } else {
        #pragma unroll
        for (int q = 0; q < K; q++) dst[q] = 0ull;
    }
}

__global__ __launch_bounds__(T1, 2) void beam_topk(
    const float* __restrict__ lprobs,
    const float* __restrict__ scores,
    const int*   __restrict__ mask,
    const int*   __restrict__ step_ptr,
    float*       __restrict__ out)
{
    const int chunk = blockIdx.x;
    const int beam  = blockIdx.y;
    const int row   = blockIdx.z;
    const int tid   = threadIdx.x;
    const int warp  = tid >> 5;
    const int lane  = tid & 31;
    const int bb    = row * BEAM + beam;

    const int step  = step_ptr ? step_ptr[0] : STEPDIM;

    __shared__ ull sh[8 * K];
    __shared__ int s_last;

    // ---------- scan phase (kept beams only; others contribute analytically) ----------
    const int* m = mask + bb * NGRAM;
    const bool keep = (m[0] + m[1] + m[2] + m[3]) == NGRAM;
    const bool active = keep && !(step == 0 && beam != 0);

    if (active) {
        const float bias = (step == 0) ? 0.0f : scores[bb * STEPDIM + (step - 1)];
        const unsigned int flatbase = (unsigned)beam * VOCAB;
        const int start = chunk * CHUNK;
        const int end   = min(VOCAB, start + CHUNK);
        const float* lp = lprobs + (size_t)bb * VOCAB;

        ull best[K];
        #pragma unroll
        for (int i = 0; i < K; i++) best[i] = 0ull;
        unsigned int curmin_hi = 0u;   // enc(value) of current 16th

        int i = start + tid;
        for (; i + 3 * T1 < end; i += 4 * T1) {
            float v0 = lp[i];
            float v1 = lp[i +     T1];
            float v2 = lp[i + 2 * T1];
            float v3 = lp[i + 3 * T1];
            unsigned int e0 = enc_f32(v0 + bias);
            unsigned int e1 = enc_f32(v1 + bias);
            unsigned int e2 = enc_f32(v2 + bias);
            unsigned int e3 = enc_f32(v3 + bias);
            if (e0 >= curmin_hi) { insert16(best, make_key_enc(e0, flatbase + (unsigned)i));           curmin_hi = (unsigned)(best[K-1] >> 32); }
            if (e1 >= curmin_hi) { insert16(best, make_key_enc(e1, flatbase + (unsigned)(i +     T1))); curmin_hi = (unsigned)(best[K-1] >> 32); }
            if (e2 >= curmin_hi) { insert16(best, make_key_enc(e2, flatbase + (unsigned)(i + 2 * T1))); curmin_hi = (unsigned)(best[K-1] >> 32); }
            if (e3 >= curmin_hi) { insert16(best, make_key_enc(e3, flatbase + (unsigned)(i + 3 * T1))); curmin_hi = (unsigned)(best[K-1] >> 32); }
        }
        for (; i < end; i += T1) {
            unsigned int e = enc_f32(lp[i] + bias);
            if (e >= curmin_hi) { insert16(best, make_key_enc(e, flatbase + (unsigned)i)); curmin_hi = (unsigned)(best[K-1] >> 32); }
        }

        // warp reduce: 5 bitonic merge rounds
        warp_merge_round(best, 1);
        warp_merge_round(best, 2);
        warp_merge_round(best, 4);
        warp_merge_round(best, 8);
        warp_merge_round(best, 16);

        if (lane == 0) {
            #pragma unroll
            for (int q = 0; q < K; q++) sh[warp * K + q] = best[q];
        }
        __syncthreads();
        if (warp == 0) {
            ull v[K];
            const int src = lane & 7;
            #pragma unroll
            for (int q = 0; q < K; q++) v[q] = sh[src * K + q];
            warp_merge_round(v, 1);
            warp_merge_round(v, 2);
            warp_merge_round(v, 4);
            // transposed write: lane q -> g_scratch[row][q][beam*8+chunk]
            if (lane < K) {
                const int l = beam * SPLIT + chunk;
                g_scratch[(size_t)row * (K * NLIST) + lane * NLIST + l] =
                    select_lane(v, lane);
            }
            __syncwarp();
        }
    }

    // ---------- arrival: every block of the row arrives exactly once ----------
    __syncthreads();
    if (tid == 0) {
        __threadfence();
        unsigned c = atomicAdd(&g_count[row], 1u);
        s_last = (c == (unsigned)(NLIST - 1));
    }
    __syncthreads();
    if (!s_last) return;

    // ---------- merge phase: last block of the row merges all 64 lists ----------
    if (tid == 0) g_count[row] = 0u;   // reset for next graph replay
    if (warp != 0) return;
    __threadfence();                    // acquire: see all rows' scratch writes

    // lanes 0..7: per-beam keep + bias
    bool kb = false; float mybias = 0.0f;
    if (lane < BEAM) {
        const int* mm = mask + (row * BEAM + lane) * NGRAM;
        kb = (mm[0] + mm[1] + mm[2] + mm[3]) == NGRAM;
        mybias = (step == 0) ? 0.0f
                             : scores[(row * BEAM + lane) * STEPDIM + (step - 1)];
    }
    const unsigned keepmask = __ballot_sync(0xffffffffu, kb) & 0xffu;

    const ull* rowbase = g_scratch + (size_t)row * (K * NLIST);
    const int lA = lane, lB = lane + 32;
    const float biasA = __shfl_sync(0xffffffffu, mybias, lA >> 3);
    const float biasB = __shfl_sync(0xffffffffu, mybias, lB >> 3);

    ull v[K];
    build_list(v, rowbase, lA, step, keepmask, biasA);
    {
        ull b[K];
        build_list(b, rowbase, lB, step, keepmask, biasB);
        #pragma unroll
        for (int q = 0; q < K; q++) {
            ull o = b[K - 1 - q];
            v[q] = v[q] > o ? v[q] : o;
        }
        bitonic16_desc(v);
    }
    warp_merge_round(v, 1);
    warp_merge_round(v, 2);
    warp_merge_round(v, 4);
    warp_merge_round(v, 8);
    warp_merge_round(v, 16);
    // every lane now holds the row's sorted top-16

    if (lane < K) {
        ull key = select_lane(v, lane);
        unsigned int hi = (unsigned)(key >> 32);
        unsigned int lo = (unsigned)key;
        unsigned int u  = (hi & 0x80000000u) ? (hi ^ 0x80000000u) : ~hi;
        float val = __uint_as_float(u);
        unsigned int flat = ~lo;
        unsigned int bsel = flat / VOCAB;
        unsigned int vsel = flat - bsel * VOCAB;

        out[              row * K + lane] = val;           // scores_buf
        out[BSZ * K     + row * K + lane] = (float)vsel;   // indices_buf
        out[2 * BSZ * K + row * K + lane] = (float)bsel;   // beams_buf
    }
}

extern "C" void kernel_launch(void* const* d_in, const int* in_sizes, int n_in,
                              void* d_out, int out_size) {
    (void)in_sizes; (void)out_size;
    const float* lprobs = (const float*)d_in[0];
    const float* scores = (const float*)d_in[1];
    const int*   mask   = (const int*)d_in[2];
    const int*   step   = (n_in > 3) ? (const int*)d_in[3] : nullptr;

    dim3 g(SPLIT, BEAM, BSZ);
    beam_topk<<<g, T1>>>(lprobs, scores, mask, step, (float*)d_out);
}

// round 11
// speedup vs baseline: 1.1322x; 1.1322x over previous
#include <cuda_runtime.h>
#include <cfloat>

#define VOCAB   50257
#define BEAM    8
#define BSZ     64
#define K       16
#define NGRAM   4
#define STEPDIM 16
#define SPLIT   4
#define NLIST   (BEAM * SPLIT)      // 32 lists per row
#define T1      256
#define NBLK2   304                 // 152 SMs x 2 persistent blocks

typedef unsigned long long ull;

// Scratch: [q][row][list] so merge lane==list loads are coalesced (256B/row).
__device__ ull      g_scratch[K * BSZ * NLIST];
__device__ int      g_work[BSZ * BEAM];      // compacted kept (row*8+beam)
__device__ unsigned g_nwork;                 // overwritten by prep each replay
__device__ int      g_keepmask[BSZ];         // 8-bit keep mask per row

// Monotone float -> uint32 encode: a > b  <=>  enc(a) > enc(b)
__device__ __forceinline__ unsigned enc_f32(float v) {
    unsigned u = __float_as_uint(v);
    return (u & 0x80000000u) ? ~u : (u | 0x80000000u);
}
// Key = [enc(value):32 | ~flat_index:32]: bigger = bigger value, then smaller
// index (lax.top_k stable tie-break). Unique per row.
__device__ __forceinline__ ull make_key_enc(unsigned ev, unsigned flat) {
    return ((ull)ev << 32) | (unsigned)(~flat);
}
#define SENTINEL_HI 0x00800000u      // enc(-FLT_MAX): below any real value

// Sort a bitonic 16-sequence descending (static indexing -> registers).
__device__ __forceinline__ void bitonic16_desc(ull v[K]) {
    #pragma unroll
    for (int d = 8; d >= 1; d >>= 1) {
        #pragma unroll
        for (int i = 0; i < K; i++) {
            if ((i & d) == 0) {
                ull a = v[i], b = v[i | d];
                v[i]     = a > b ? a : b;
                v[i | d] = a > b ? b : a;
            }
        }
    }
}
// Merge own sorted-desc 16-list with xor-partner's -> top-16 of union, desc.
__device__ __forceinline__ void warp_merge_round(ull v[K], int o) {
    ull other[K];
    #pragma unroll
    for (int i = 0; i < K; i++)
        other[i] = __shfl_xor_sync(0xffffffffu, v[K - 1 - i], o);
    #pragma unroll
    for (int i = 0; i < K; i++)
        v[i] = v[i] > other[i] ? v[i] : other[i];
    bitonic16_desc(v);
}
// Unrolled insert into sorted-desc 16-list (registers only).
__device__ __forceinline__ void insert16(ull best[K], ull key) {
    ull x = key;
    #pragma unroll
    for (int j = 0; j < K; j++) {
        ull mx = best[j] > x ? best[j] : x;
        ull mn = best[j] > x ? x : best[j];
        best[j] = mx;
        x = mn;
    }
}
__device__ __forceinline__ ull select_lane(const ull v[K], int lane) {
    ull r = v[0];
    #pragma unroll
    for (int j = 1; j < K; j++) if (lane == j) r = v[j];
    return r;
}

// Exact-path insert: 64-bit key compare; updates conservative float threshold.
__device__ __forceinline__ void proc_exact(ull best[K], unsigned &curmin_hi,
                                           float &thresh, float v, float bias,
                                           unsigned flat) {
    unsigned e = enc_f32(v + bias);
    if (e > curmin_hi) {                      // strict: equal value -> later idx loses
        insert16(best, make_key_enc(e, flat));
        curmin_hi = (unsigned)(best[K - 1] >> 32);
        unsigned u = (curmin_hi & 0x80000000u) ? (curmin_hi ^ 0x80000000u)
                                               : ~curmin_hi;
        float c = __uint_as_float(u);
        float t = c - bias;
        // Slack covers the two roundings (add + sub): borderline -> slow path.
        thresh = t - (fabsf(c) + fabsf(bias)) * 5e-7f - 1e-37f;
    }
}

// ---------------- K1: compact kept beams + per-row keep masks ----------------
__global__ __launch_bounds__(512) void prep(const int* __restrict__ mask) {
    const int bb = threadIdx.x;               // 512 = BSZ*BEAM
    const int lane = bb & 31, warp = bb >> 5;
    const int4 mm = ((const int4*)mask)[bb];
    const bool keep = (mm.x + mm.y + mm.z + mm.w) == NGRAM;
    unsigned bal = __ballot_sync(0xffffffffu, keep);

    __shared__ int wcnt[16], wbase[16];
    if (lane == 0) wcnt[warp] = __popc(bal);
    __syncthreads();
    if (bb == 0) {
        int s = 0;
        for (int w = 0; w < 16; w++) { wbase[w] = s; s += wcnt[w]; }
        g_nwork = (unsigned)s;
    }
    __syncthreads();
    if (keep) g_work[wbase[warp] + __popc(bal & ((1u << lane) - 1u))] = bb;
    if ((bb & 7) == 0)
        g_keepmask[bb >> 3] = (int)((bal >> (lane & 24)) & 0xffu);
}

// ---------------- K2: persistent scan of kept beams ----------------
__global__ __launch_bounds__(T1, 2) void scan_topk(
    const float* __restrict__ lprobs,
    const float* __restrict__ scores,
    const int*   __restrict__ step_ptr)
{
    const int tid = threadIdx.x, warp = tid >> 5, lane = tid & 31;
    const int step = step_ptr ? step_ptr[0] : STEPDIM;
    const int total = (int)g_nwork * SPLIT;
    __shared__ ull sh[8 * K];

    for (int item = blockIdx.x; item < total; item += gridDim.x) {
        const int bb    = g_work[item >> 2];
        const int chunk = item & 3;
        const int row = bb >> 3, beam = bb & 7;
        if (step == 0 && beam != 0) continue;          // uniform per block

        const float bias = (step == 0) ? 0.0f : scores[bb * STEPDIM + step - 1];
        const unsigned flatbase = (unsigned)beam * VOCAB;
        const float* lp = lprobs + (size_t)bb * VOCAB;

        // Align to 16B for float4 loads; chunk 0 handles the scalar prefix.
        const int pad  = (4 - ((bb * VOCAB) & 3)) & 3;
        const float4* fp4 = (const float4*)(lp + pad);
        const int nq   = (VOCAB - pad) >> 2;
        const int tail = VOCAB - pad - nq * 4;
        const int qpc  = (nq + SPLIT - 1) / SPLIT;
        const int q0 = chunk * qpc, q1 = min(nq, q0 + qpc);

        ull best[K];
        #pragma unroll
        for (int i = 0; i < K; i++) best[i] = (ull)SENTINEL_HI << 32;
        unsigned curmin_hi = SENTINEL_HI;
        float thresh = -FLT_MAX;

        if (chunk == 0 && tid < pad)
            proc_exact(best, curmin_hi, thresh, lp[tid], bias, flatbase + tid);

        for (int q = q0 + tid; q < q1; q += T1) {
            float4 x = fp4[q];
            float m = fmaxf(fmaxf(x.x, x.y), fmaxf(x.z, x.w));
            if (m > thresh) {                 // rare after warm-up
                unsigned b = flatbase + (unsigned)(pad + 4 * q);
                proc_exact(best, curmin_hi, thresh, x.x, bias, b);
                proc_exact(best, curmin_hi, thresh, x.y, bias, b + 1);
                proc_exact(best, curmin_hi, thresh, x.z, bias, b + 2);
                proc_exact(best, curmin_hi, thresh, x.w, bias, b + 3);
            }
        }
        if (chunk == SPLIT - 1 && tid < tail) {
            int idx = pad + nq * 4 + tid;
            proc_exact(best, curmin_hi, thresh, lp[idx], bias, flatbase + idx);
        }

        // Warp reduce: 5 bitonic merge rounds.
        warp_merge_round(best, 1);
        warp_merge_round(best, 2);
        warp_merge_round(best, 4);
        warp_merge_round(best, 8);
        warp_merge_round(best, 16);

        if (lane == 0) {
            #pragma unroll
            for (int q = 0; q < K; q++) sh[warp * K + q] = best[q];
        }
        __syncthreads();
        if (warp == 0) {
            ull v[K];
            const int src = lane & 7;
            #pragma unroll
            for (int q = 0; q < K; q++) v[q] = sh[src * K + q];
            warp_merge_round(v, 1);
            warp_merge_round(v, 2);
            warp_merge_round(v, 4);
            if (lane < K) {
                const int l = beam * SPLIT + chunk;
                g_scratch[(size_t)lane * (BSZ * NLIST) + row * NLIST + l] =
                    select_lane(v, lane);
            }
        }
        __syncthreads();                       // shared reuse across items
    }
}

// ---------------- K3: per-row merge of 32 lists ----------------
__global__ __launch_bounds__(256) void merge_topk(
    const float* __restrict__ scores,
    const int*   __restrict__ step_ptr,
    float*       __restrict__ out)
{
    const int w = threadIdx.x >> 5, lane = threadIdx.x & 31;
    const int row = blockIdx.x * 8 + w;
    const int step = step_ptr ? step_ptr[0] : STEPDIM;
    const int keepmask = g_keepmask[row];

    float mybias = 0.0f;
    if (lane < BEAM && step > 0)
        mybias = scores[(row * BEAM + lane) * STEPDIM + step - 1];

    const int l = lane, beam = l >> 2, chunk = l & 3;
    const float biasL = __shfl_sync(0xffffffffu, mybias, beam);
    const bool valid = !(step == 0 && beam != 0);
    const bool kb = (keepmask >> beam) & 1;

    ull v[K];
    if (valid && kb) {                         // coalesced: lane==list
        #pragma unroll
        for (int q = 0; q < K; q++)
            v[q] = g_scratch[(size_t)q * (BSZ * NLIST) + row * NLIST + l];
    } else if (valid && chunk == 0) {          // constant beam: analytic top-16
        const unsigned ev = enc_f32(biasL);
        #pragma unroll
        for (int q = 0; q < K; q++)
            v[q] = make_key_enc(ev, (unsigned)beam * VOCAB + (unsigned)q);
    } else {
        #pragma unroll
        for (int q = 0; q < K; q++) v[q] = 0ull;
    }

    warp_merge_round(v, 1);
    warp_merge_round(v, 2);
    warp_merge_round(v, 4);
    warp_merge_round(v, 8);
    warp_merge_round(v, 16);
    // every lane holds the row's sorted top-16

    if (lane < K) {
        ull key = select_lane(v, lane);
        unsigned hi = (unsigned)(key >> 32);
        unsigned lo = (unsigned)key;
        unsigned u  = (hi & 0x80000000u) ? (hi ^ 0x80000000u) : ~hi;
        float val = __uint_as_float(u);
        unsigned flat = ~lo;
        unsigned bsel = flat / VOCAB;
        unsigned vsel = flat - bsel * VOCAB;

        out[              row * K + lane] = val;           // scores_buf
        out[BSZ * K     + row * K + lane] = (float)vsel;   // indices_buf
        out[2 * BSZ * K + row * K + lane] = (float)bsel;   // beams_buf
    }
}

extern "C" void kernel_launch(void* const* d_in, const int* in_sizes, int n_in,
                              void* d_out, int out_size) {
    (void)in_sizes; (void)out_size;
    const float* lprobs = (const float*)d_in[0];
    const float* scores = (const float*)d_in[1];
    const int*   mask   = (const int*)d_in[2];
    const int*   step   = (n_in > 3) ? (const int*)d_in[3] : nullptr;

    prep<<<1, 512>>>(mask);
    scan_topk<<<NBLK2, T1>>>(lprobs, scores, step);
    merge_topk<<<BSZ / 8, 256>>>(scores, step, (float*)d_out);
}

// round 14
// speedup vs baseline: 2.0708x; 1.8290x over previous
#include <cuda_runtime.h>
#include <cfloat>

#define VOCAB   50257
#define BEAM    8
#define BSZ     64
#define K       16
#define NGRAM   4
#define STEPDIM 16
#define T       512
#define NW      (T / 32)      // 16 warps

typedef unsigned long long ull;

// Monotone float -> uint32 encode: a > b  <=>  enc(a) > enc(b)
__device__ __forceinline__ unsigned enc_f32(float v) {
    unsigned u = __float_as_uint(v);
    return (u & 0x80000000u) ? ~u : (u | 0x80000000u);
}
// Key = [enc(value):32 | ~flat_index:32]: bigger = bigger value, then smaller
// flat index (lax.top_k stable tie-break). Unique per row.
__device__ __forceinline__ ull make_key_enc(unsigned ev, unsigned flat) {
    return ((ull)ev << 32) | (unsigned)(~flat);
}

// Sort a bitonic 16-sequence descending (static indexing -> registers).
__device__ __forceinline__ void bitonic16_desc(ull v[K]) {
    #pragma unroll
    for (int d = 8; d >= 1; d >>= 1) {
        #pragma unroll
        for (int i = 0; i < K; i++) {
            if ((i & d) == 0) {
                ull a = v[i], b = v[i | d];
                v[i]     = a > b ? a : b;
                v[i | d] = a > b ? b : a;
            }
        }
    }
}
// Merge own sorted-desc 16-list with xor-partner's -> top-16 of union, desc.
__device__ __forceinline__ void warp_merge_round(ull v[K], int o) {
    ull other[K];
    #pragma unroll
    for (int i = 0; i < K; i++)
        other[i] = __shfl_xor_sync(0xffffffffu, v[K - 1 - i], o);
    #pragma unroll
    for (int i = 0; i < K; i++)
        v[i] = v[i] > other[i] ? v[i] : other[i];
    bitonic16_desc(v);
}
// Unrolled insert into sorted-desc 16-list (registers only).
__device__ __forceinline__ void insert16(ull best[K], ull key) {
    ull x = key;
    #pragma unroll
    for (int j = 0; j < K; j++) {
        ull mx = best[j] > x ? best[j] : x;
        ull mn = best[j] > x ? x : best[j];
        best[j] = mx;
        x = mn;
    }
}
__device__ __forceinline__ ull select_lane(const ull v[K], int lane) {
    ull r = v[0];
    #pragma unroll
    for (int j = 1; j < K; j++) if (lane == j) r = v[j];
    return r;
}
// Exact candidate insert (value already bias-applied at float level exactly
// as the reference computes it: lprobs + bias).
__device__ __forceinline__ void cand(ull best[K], unsigned &curmin_hi,
                                     float v, unsigned flat) {
    unsigned e = enc_f32(v);
    if (e > curmin_hi) {   // equal value -> later index loses: skip is exact
        insert16(best, make_key_enc(e, flat));
        curmin_hi = (unsigned)(best[K - 1] >> 32);
    }
}

__global__ __launch_bounds__(T, 1) void beam_topk(
    const float* __restrict__ lprobs,
    const float* __restrict__ scores,
    const int*   __restrict__ mask,
    const int*   __restrict__ step_ptr,
    float*       __restrict__ out)
{
    const int row  = blockIdx.x;
    const int tid  = threadIdx.x;
    const int warp = tid >> 5, lane = tid & 31;
    const int step = step_ptr ? step_ptr[0] : STEPDIM;
    const int nbeam = (step == 0) ? 1 : BEAM;

    __shared__ float s_wmax[NW];
    __shared__ float s_bias[BEAM];
    __shared__ int   s_keep;

    if (tid < BEAM) {
        const int bb = row * BEAM + tid;
        const int4 mm = ((const int4*)mask)[bb];
        const bool kp = (mm.x + mm.y + mm.z + mm.w) == NGRAM;
        unsigned bal = __ballot_sync(0xffu, kp);
        if (tid == 0) s_keep = (int)bal;
        s_bias[tid] = (step == 0) ? 0.0f : scores[bb * STEPDIM + (step - 1)];
    }
    __syncthreads();
    const int keepmask = s_keep;

    // Per-thread top-16 across ALL beams of this row (keys globally ordered).
    ull best[K];
    #pragma unroll
    for (int i = 0; i < K; i++) best[i] = 0ull;   // below any real key
    unsigned curmin_hi = 0u;

    for (int b = 0; b < nbeam; b++) {
        const float bias = s_bias[b];
        const unsigned flatbase = (unsigned)b * VOCAB;

        if (!((keepmask >> b) & 1)) {
            // Non-kept beam is constant (= bias): its top-16 is analytically
            // the first 16 indices. Threads 0..15 insert one key each.
            if (tid < K)
                cand(best, curmin_hi, bias, flatbase + (unsigned)tid);
            continue;
        }

        const int bb = row * BEAM + b;
        const float* lp = lprobs + (size_t)bb * VOCAB;
        const int pad  = (4 - (bb & 3)) & 3;      // VOCAB%4==1 -> offset%4==bb%4
        const float4* fp4 = (const float4*)(lp + pad);
        const int nq   = (VOCAB - pad) >> 2;
        const int tail = VOCAB - pad - 4 * nq;

        // ---- pass A: per-thread raw max (no inserts, pure streaming) ----
        float tm = -FLT_MAX;
        if (tid < pad)  tm = lp[tid];
        if (tid < tail) tm = fmaxf(tm, lp[pad + 4 * nq + tid]);
        for (int q = tid; q < nq; q += T) {
            float4 x = fp4[q];
            tm = fmaxf(tm, fmaxf(fmaxf(x.x, x.y), fmaxf(x.z, x.w)));
        }
        #pragma unroll
        for (int o = 16; o > 0; o >>= 1)
            tm = fmaxf(tm, __shfl_xor_sync(0xffffffffu, tm, o));
        if (lane == 0) s_wmax[warp] = tm;
        __syncthreads();
        // threshold m = min of 16 warp maxes: >=16 elements >= m  =>  m <= v16
        float m = s_wmax[0];
        #pragma unroll
        for (int w = 1; w < NW; w++) m = fminf(m, s_wmax[w]);
        __syncthreads();    // s_wmax reused next beam

        // ---- pass B: L2-hot re-stream; only v >= m enters exact path ----
        if (tid < pad && lp[tid] >= m)
            cand(best, curmin_hi, lp[tid] + bias, flatbase + (unsigned)tid);
        if (tid < tail) {
            const int idx = pad + 4 * nq + tid;
            if (lp[idx] >= m)
                cand(best, curmin_hi, lp[idx] + bias, flatbase + (unsigned)idx);
        }
        for (int q = tid; q < nq; q += T) {
            float4 x = fp4[q];
            float mx = fmaxf(fmaxf(x.x, x.y), fmaxf(x.z, x.w));
            if (mx >= m) {                       // ~1-50 hits per beam total
                const unsigned bi = flatbase + (unsigned)(pad + 4 * q);
                if (x.x >= m) cand(best, curmin_hi, x.x + bias, bi);
                if (x.y >= m) cand(best, curmin_hi, x.y + bias, bi + 1);
                if (x.z >= m) cand(best, curmin_hi, x.z + bias, bi + 2);
                if (x.w >= m) cand(best, curmin_hi, x.w + bias, bi + 3);
            }
        }
    }

    // ---- final: 512 lists -> 16 warp lists -> 1 block list ----
    warp_merge_round(best, 1);
    warp_merge_round(best, 2);
    warp_merge_round(best, 4);
    warp_merge_round(best, 8);
    warp_merge_round(best, 16);

    __shared__ ull s_lists[NW * K];
    if (lane == 0) {
        #pragma unroll
        for (int q = 0; q < K; q++) s_lists[warp * K + q] = best[q];
    }
    __syncthreads();

    if (warp == 0) {
        ull v[K];
        const int src = lane & 15;
        #pragma unroll
        for (int q = 0; q < K; q++) v[q] = s_lists[src * K + q];
        warp_merge_round(v, 1);
        warp_merge_round(v, 2);
        warp_merge_round(v, 4);
        warp_merge_round(v, 8);
        // lanes 0-15 all hold the row's sorted top-16

        if (lane < K) {
            ull key = select_lane(v, lane);
            unsigned hi = (unsigned)(key >> 32);
            unsigned lo = (unsigned)key;
            unsigned u  = (hi & 0x80000000u) ? (hi ^ 0x80000000u) : ~hi;
            float val = __uint_as_float(u);
            unsigned flat = ~lo;
            unsigned bsel = flat / VOCAB;
            unsigned vsel = flat - bsel * VOCAB;

            out[              row * K + lane] = val;           // scores_buf
            out[BSZ * K     + row * K + lane] = (float)vsel;   // indices_buf
            out[2 * BSZ * K + row * K + lane] = (float)bsel;   // beams_buf
        }
    }
}

extern "C" void kernel_launch(void* const* d_in, const int* in_sizes, int n_in,
                              void* d_out, int out_size) {
    (void)in_sizes; (void)out_size;
    const float* lprobs = (const float*)d_in[0];
    const float* scores = (const float*)d_in[1];
    const int*   mask   = (const int*)d_in[2];
    const int*   step   = (n_in > 3) ? (const int*)d_in[3] : nullptr;

    beam_topk<<<BSZ, T>>>(lprobs, scores, mask, step, (float*)d_out);
}